// round 2
// baseline (speedup 1.0000x reference)
#include <cuda_runtime.h>

#define N_NODES 50000
#define N_EDGES 800000
#define F 256

#define BM 128
#define BN 64
#define BK 16

// ---------------- scratch (no allocations allowed) ----------------
__device__ __align__(16) float g_agg [N_NODES * F];
__device__ __align__(16) float g_bufA[N_NODES * F];
__device__ __align__(16) float g_bufB[N_NODES * F];
__device__ int g_deg[N_NODES];
__device__ int g_row[N_NODES + 1];
__device__ int g_cur[N_NODES];
__device__ int g_csr[N_EDGES];

// ---------------- CSR build ----------------
__global__ void k_zero_deg(int n) {
    int i = blockIdx.x * blockDim.x + threadIdx.x;
    if (i < n) g_deg[i] = 0;
}

__global__ void k_count(const int* __restrict__ dst, int e) {
    int i = blockIdx.x * blockDim.x + threadIdx.x;
    if (i < e) atomicAdd(&g_deg[dst[i]], 1);
}

// single-block exclusive scan over g_deg -> g_row (n = 50000, ~49 chunks of 1024)
__global__ void k_scan(int n) {
    __shared__ int sm[1024];
    __shared__ int carry;
    if (threadIdx.x == 0) { carry = 0; g_row[0] = 0; }
    __syncthreads();
    for (int base = 0; base < n; base += 1024) {
        int i = base + threadIdx.x;
        int v = (i < n) ? g_deg[i] : 0;
        sm[threadIdx.x] = v;
        __syncthreads();
        for (int off = 1; off < 1024; off <<= 1) {
            int t = (threadIdx.x >= off) ? sm[threadIdx.x - off] : 0;
            __syncthreads();
            sm[threadIdx.x] += t;
            __syncthreads();
        }
        int incl = sm[threadIdx.x] + carry;
        if (i < n) g_row[i + 1] = incl;
        __syncthreads();
        if (threadIdx.x == 1023) carry = incl;
        __syncthreads();
    }
}

__global__ void k_init_cur(int n) {
    int i = blockIdx.x * blockDim.x + threadIdx.x;
    if (i < n) g_cur[i] = g_row[i];
}

__global__ void k_fill(const int* __restrict__ src, const int* __restrict__ dst, int e) {
    int i = blockIdx.x * blockDim.x + threadIdx.x;
    if (i < e) {
        int p = atomicAdd(&g_cur[dst[i]], 1);
        g_csr[p] = src[i];
    }
}

// ---------------- mean aggregation (gather over CSR) ----------------
// blockDim = (64, 4): threadIdx.x covers 256 floats as 64 float4; 4 nodes/block.
__global__ void k_agg(const float* __restrict__ h, float* __restrict__ agg, int n) {
    int v = blockIdx.x * 4 + threadIdx.y;
    if (v >= n) return;
    int s = g_row[v], e = g_row[v + 1];
    const float4* h4 = (const float4*)h;
    int tx = threadIdx.x;
    float4 acc = make_float4(0.f, 0.f, 0.f, 0.f);
    for (int i = s; i < e; i++) {
        int u = g_csr[i];
        float4 t = __ldg(&h4[u * 64 + tx]);
        acc.x += t.x; acc.y += t.y; acc.z += t.z; acc.w += t.w;
    }
    float inv = 1.0f / (float)max(e - s, 1);
    acc.x *= inv; acc.y *= inv; acc.z *= inv; acc.w *= inv;
    ((float4*)agg)[v * 64 + tx] = acc;
}

// ---------------- fused dual GEMM: out = X1@W1^T + X2@W2^T + b (opt relu) ----
// W layout [Nout, Kd] row-major. Register-tiled fp32: BM=128, BN=64, BK=16,
// 256 threads, 8x4 micro-tile per thread.
__global__ __launch_bounds__(256) void k_gemm(
    const float* __restrict__ X1, const float* __restrict__ X2,
    const float* __restrict__ W1, const float* __restrict__ W2,
    const float* __restrict__ bias, float* __restrict__ out,
    int M, int Nout, int Kd, int relu)
{
    __shared__ float As[BK][BM];
    __shared__ float Bs[BK][BN];

    int tid = threadIdx.x;
    int bm = blockIdx.x * BM;
    int bn = blockIdx.y * BN;
    int tm0 = (tid >> 4) * 8;   // 0..120
    int tn0 = (tid & 15) * 4;   // 0..60

    float acc[8][4];
#pragma unroll
    for (int i = 0; i < 8; i++)
#pragma unroll
        for (int j = 0; j < 4; j++) acc[i][j] = 0.f;

    int lr = tid >> 2;          // 0..63
    int lk = (tid & 3) * 4;     // 0,4,8,12

    for (int p = 0; p < 2; ++p) {
        const float* X = p ? X2 : X1;
        const float* W = p ? W2 : W1;
        for (int kk = 0; kk < Kd; kk += BK) {
            // A tile: rows bm..bm+127, cols kk..kk+15, stored transposed
#pragma unroll
            for (int rr = 0; rr < 2; rr++) {
                int row = bm + lr + rr * 64;
                float4 v = make_float4(0.f, 0.f, 0.f, 0.f);
                if (row < M) v = *(const float4*)&X[row * Kd + kk + lk];
                As[lk + 0][lr + rr * 64] = v.x;
                As[lk + 1][lr + rr * 64] = v.y;
                As[lk + 2][lr + rr * 64] = v.z;
                As[lk + 3][lr + rr * 64] = v.w;
            }
            // B tile: W rows bn..bn+63 (Nout multiple of 64 -> no guard)
            {
                float4 v = *(const float4*)&W[(bn + lr) * Kd + kk + lk];
                Bs[lk + 0][lr] = v.x;
                Bs[lk + 1][lr] = v.y;
                Bs[lk + 2][lr] = v.z;
                Bs[lk + 3][lr] = v.w;
            }
            __syncthreads();
#pragma unroll
            for (int k = 0; k < BK; k++) {
                float4 a0 = *(const float4*)&As[k][tm0];
                float4 a1 = *(const float4*)&As[k][tm0 + 4];
                float4 bv = *(const float4*)&Bs[k][tn0];
                float a[8] = {a0.x, a0.y, a0.z, a0.w, a1.x, a1.y, a1.z, a1.w};
                float b[4] = {bv.x, bv.y, bv.z, bv.w};
#pragma unroll
                for (int i = 0; i < 8; i++)
#pragma unroll
                    for (int j = 0; j < 4; j++)
                        acc[i][j] += a[i] * b[j];
            }
            __syncthreads();
        }
    }

    float4 bb = *(const float4*)&bias[bn + tn0];
#pragma unroll
    for (int i = 0; i < 8; i++) {
        int row = bm + tm0 + i;
        if (row < M) {
            float4 v;
            v.x = acc[i][0] + bb.x;
            v.y = acc[i][1] + bb.y;
            v.z = acc[i][2] + bb.z;
            v.w = acc[i][3] + bb.w;
            if (relu) {
                v.x = fmaxf(v.x, 0.f); v.y = fmaxf(v.y, 0.f);
                v.z = fmaxf(v.z, 0.f); v.w = fmaxf(v.w, 0.f);
            }
            *(float4*)&out[row * Nout + bn + tn0] = v;
        }
    }
}

// ---------------- host ----------------
extern "C" void kernel_launch(void* const* d_in, const int* in_sizes, int n_in,
                              void* d_out, int out_size) {
    // Classify inputs by element count (robust to dict-order vs signature-order).
    const float* x = nullptr;
    const int *src = nullptr, *dstp = nullptr;
    const float* Ws[3] = {0, 0, 0};
    const float* Wn[3] = {0, 0, 0};
    const float* bs[3] = {0, 0, 0};
    int c65536 = 0, c256 = 0, c32768 = 0, c800k = 0;
    for (int i = 0; i < n_in; i++) {
        int sz = in_sizes[i];
        void* p = d_in[i];
        if (sz == 12800000) {
            x = (const float*)p;
        } else if (sz == 800000) {
            if (c800k++ == 0) src = (const int*)p; else dstp = (const int*)p;
        } else if (sz == 65536) {
            int k = c65536++;
            if (k == 0) Ws[0] = (const float*)p;
            else if (k == 1) Wn[0] = (const float*)p;
            else if (k == 2) Ws[1] = (const float*)p;
            else Wn[1] = (const float*)p;
        } else if (sz == 32768) {
            if (c32768++ == 0) Ws[2] = (const float*)p; else Wn[2] = (const float*)p;
        } else if (sz == 256) {
            if (c256++ == 0) bs[0] = (const float*)p; else bs[1] = (const float*)p;
        } else if (sz == 128) {
            bs[2] = (const float*)p;
        }
    }

    float *agg, *bufA, *bufB;
    cudaGetSymbolAddress((void**)&agg,  g_agg);
    cudaGetSymbolAddress((void**)&bufA, g_bufA);
    cudaGetSymbolAddress((void**)&bufB, g_bufB);

    const int n = N_NODES, e = N_EDGES;

    // CSR build (per call; deterministic work)
    k_zero_deg<<<(n + 255) / 256, 256>>>(n);
    k_count<<<(e + 255) / 256, 256>>>(dstp, e);
    k_scan<<<1, 1024>>>(n);
    k_init_cur<<<(n + 255) / 256, 256>>>(n);
    k_fill<<<(e + 255) / 256, 256>>>(src, dstp, e);

    dim3 aggBlk(64, 4);
    int aggGrid = (n + 3) / 4;
    float* outp = (float*)d_out;

    dim3 g01((n + BM - 1) / BM, 256 / BN);
    dim3 g2 ((n + BM - 1) / BM, 128 / BN);

    // layer 0: in = x
    k_agg<<<aggGrid, aggBlk>>>(x, agg, n);
    k_gemm<<<g01, 256>>>(x, agg, Ws[0], Wn[0], bs[0], bufA, n, 256, 256, 1);
    // layer 1
    k_agg<<<aggGrid, aggBlk>>>(bufA, agg, n);
    k_gemm<<<g01, 256>>>(bufA, agg, Ws[1], Wn[1], bs[1], bufB, n, 256, 256, 1);
    // layer 2 (no relu) -> d_out
    k_agg<<<aggGrid, aggBlk>>>(bufB, agg, n);
    k_gemm<<<g2, 256>>>(bufB, agg, Ws[2], Wn[2], bs[2], outp, n, 128, 256, 0);
}

// round 3
// speedup vs baseline: 1.7633x; 1.7633x over previous
#include <cuda_runtime.h>
#include <cstdint>

#define N_NODES 50000
#define N_EDGES 800000
#define F 256

// ---------------- scratch (no allocations allowed) ----------------
__device__ __align__(16) float g_agg [N_NODES * F];
__device__ __align__(16) float g_bufA[N_NODES * F];
__device__ __align__(16) float g_bufB[N_NODES * F];
__device__ int g_deg[N_NODES];
__device__ int g_row[N_NODES + 1];
__device__ int g_cur[N_NODES];
__device__ int g_csr[N_EDGES];

// ---------------- CSR build ----------------
__global__ void k_count(const int* __restrict__ dst, int e) {
    int i = blockIdx.x * blockDim.x + threadIdx.x;
    if (i < e) atomicAdd(&g_deg[dst[i]], 1);
}

// single-block exclusive scan over g_deg -> g_row
__global__ void k_scan(int n) {
    __shared__ int sm[1024];
    __shared__ int carry;
    if (threadIdx.x == 0) { carry = 0; g_row[0] = 0; }
    __syncthreads();
    for (int base = 0; base < n; base += 1024) {
        int i = base + threadIdx.x;
        int v = (i < n) ? g_deg[i] : 0;
        sm[threadIdx.x] = v;
        __syncthreads();
        for (int off = 1; off < 1024; off <<= 1) {
            int t = (threadIdx.x >= off) ? sm[threadIdx.x - off] : 0;
            __syncthreads();
            sm[threadIdx.x] += t;
            __syncthreads();
        }
        int incl = sm[threadIdx.x] + carry;
        if (i < n) g_row[i + 1] = incl;
        __syncthreads();
        if (threadIdx.x == 1023) carry = incl;
        __syncthreads();
    }
}

__global__ void k_init_cur(int n) {
    int i = blockIdx.x * blockDim.x + threadIdx.x;
    if (i < n) g_cur[i] = g_row[i];
}

__global__ void k_fill(const int* __restrict__ src, const int* __restrict__ dst, int e) {
    int i = blockIdx.x * blockDim.x + threadIdx.x;
    if (i < e) {
        int p = atomicAdd(&g_cur[dst[i]], 1);
        g_csr[p] = src[i];
    }
}

// ---------------- mean aggregation (gather over CSR) ----------------
__global__ void k_agg(const float* __restrict__ h, float* __restrict__ agg, int n) {
    int v = blockIdx.x * 4 + threadIdx.y;
    if (v >= n) return;
    int s = g_row[v], e = g_row[v + 1];
    const float4* h4 = (const float4*)h;
    int tx = threadIdx.x;
    float4 acc = make_float4(0.f, 0.f, 0.f, 0.f);
    for (int i = s; i < e; i++) {
        int u = g_csr[i];
        float4 t = __ldg(&h4[u * 64 + tx]);
        acc.x += t.x; acc.y += t.y; acc.z += t.z; acc.w += t.w;
    }
    float inv = 1.0f / (float)max(e - s, 1);
    acc.x *= inv; acc.y *= inv; acc.z *= inv; acc.w *= inv;
    ((float4*)agg)[v * 64 + tx] = acc;
}

// ---------------- TF32 tensor-core dual GEMM ----------------
// out = X1@W1^T + X2@W2^T + b (opt relu). W is [Nout, Kd] row-major.
// Block tile 128(M) x 128(N) x 16(K), 8 warps in 4(M) x 2(N) grid,
// each warp computes 32x64 via 2x8 m16n8k8 tf32 mma per k-step.

__device__ __forceinline__ uint32_t f2tf32(float x) {
    uint32_t r;
    asm("cvt.rna.tf32.f32 %0, %1;" : "=r"(r) : "f"(x));
    return r;
}

__device__ __forceinline__ void mma_tf32(float* c, const uint32_t* a, const uint32_t* b) {
    asm volatile(
        "mma.sync.aligned.m16n8k8.row.col.f32.tf32.tf32.f32 "
        "{%0,%1,%2,%3}, {%4,%5,%6,%7}, {%8,%9}, {%0,%1,%2,%3};"
        : "+f"(c[0]), "+f"(c[1]), "+f"(c[2]), "+f"(c[3])
        : "r"(a[0]), "r"(a[1]), "r"(a[2]), "r"(a[3]), "r"(b[0]), "r"(b[1]));
}

#define GBM 128
#define GBN 128
#define GBK 16
#define GLD 20   // GBK + 4 pad (conflict-free: banks 20g+c unique for g<8,c<4)

__global__ __launch_bounds__(256) void k_gemm_tf32(
    const float* __restrict__ X1, const float* __restrict__ X2,
    const float* __restrict__ W1, const float* __restrict__ W2,
    const float* __restrict__ bias, float* __restrict__ out,
    int M, int Nout, int Kd, int relu)
{
    __shared__ uint32_t As[GBM * GLD];
    __shared__ uint32_t Bs[GBN * GLD];

    int tid  = threadIdx.x;
    int lane = tid & 31;
    int warp = tid >> 5;
    int wm = warp >> 1;           // 0..3 -> M offset wm*32
    int wn = warp & 1;            // 0..1 -> N offset wn*64
    int g  = lane >> 2;           // groupID 0..7
    int c  = lane & 3;            // threadID_in_group 0..3
    int bm = blockIdx.x * GBM;
    int bn = blockIdx.y * GBN;

    float acc[2][8][4];
#pragma unroll
    for (int mi = 0; mi < 2; mi++)
#pragma unroll
        for (int ni = 0; ni < 8; ni++)
#pragma unroll
            for (int r = 0; r < 4; r++) acc[mi][ni][r] = 0.f;

    // staging: thread -> (row = tid>>1, 8-float chunk at (tid&1)*8)
    int srow  = tid >> 1;
    int skoff = (tid & 1) * 8;

    for (int p = 0; p < 2; ++p) {
        const float* X = p ? X2 : X1;
        const float* W = p ? W2 : W1;
        for (int kk = 0; kk < Kd; kk += GBK) {
            // A tile
            {
                int grow = bm + srow;
                float4 v0 = make_float4(0.f, 0.f, 0.f, 0.f), v1 = v0;
                if (grow < M) {
                    const float* px = &X[grow * Kd + kk + skoff];
                    v0 = *(const float4*)px;
                    v1 = *(const float4*)(px + 4);
                }
                uint32_t* a = &As[srow * GLD + skoff];
                a[0] = f2tf32(v0.x); a[1] = f2tf32(v0.y);
                a[2] = f2tf32(v0.z); a[3] = f2tf32(v0.w);
                a[4] = f2tf32(v1.x); a[5] = f2tf32(v1.y);
                a[6] = f2tf32(v1.z); a[7] = f2tf32(v1.w);
            }
            // B tile (Nout multiple of 128 -> no guard)
            {
                const float* pw = &W[(bn + srow) * Kd + kk + skoff];
                float4 v0 = *(const float4*)pw;
                float4 v1 = *(const float4*)(pw + 4);
                uint32_t* b = &Bs[srow * GLD + skoff];
                b[0] = f2tf32(v0.x); b[1] = f2tf32(v0.y);
                b[2] = f2tf32(v0.z); b[3] = f2tf32(v0.w);
                b[4] = f2tf32(v1.x); b[5] = f2tf32(v1.y);
                b[6] = f2tf32(v1.z); b[7] = f2tf32(v1.w);
            }
            __syncthreads();

#pragma unroll
            for (int ks = 0; ks < GBK; ks += 8) {
                uint32_t af[2][4];
#pragma unroll
                for (int mi = 0; mi < 2; mi++) {
                    int r0 = wm * 32 + mi * 16 + g;
                    af[mi][0] = As[r0 * GLD + ks + c];
                    af[mi][1] = As[(r0 + 8) * GLD + ks + c];
                    af[mi][2] = As[r0 * GLD + ks + c + 4];
                    af[mi][3] = As[(r0 + 8) * GLD + ks + c + 4];
                }
                uint32_t bf[8][2];
#pragma unroll
                for (int ni = 0; ni < 8; ni++) {
                    int n0 = wn * 64 + ni * 8 + g;
                    bf[ni][0] = Bs[n0 * GLD + ks + c];
                    bf[ni][1] = Bs[n0 * GLD + ks + c + 4];
                }
#pragma unroll
                for (int mi = 0; mi < 2; mi++)
#pragma unroll
                    for (int ni = 0; ni < 8; ni++)
                        mma_tf32(acc[mi][ni], af[mi], bf[ni]);
            }
            __syncthreads();
        }
    }

    // epilogue: c0,c1 -> row g, cols 2c,2c+1 ; c2,c3 -> row g+8
#pragma unroll
    for (int mi = 0; mi < 2; mi++) {
        int r0 = bm + wm * 32 + mi * 16 + g;
        int r1 = r0 + 8;
#pragma unroll
        for (int ni = 0; ni < 8; ni++) {
            int col = bn + wn * 64 + ni * 8 + 2 * c;
            float bx = bias[col], by = bias[col + 1];
            float v0 = acc[mi][ni][0] + bx;
            float v1 = acc[mi][ni][1] + by;
            float v2 = acc[mi][ni][2] + bx;
            float v3 = acc[mi][ni][3] + by;
            if (relu) {
                v0 = fmaxf(v0, 0.f); v1 = fmaxf(v1, 0.f);
                v2 = fmaxf(v2, 0.f); v3 = fmaxf(v3, 0.f);
            }
            if (r0 < M) *(float2*)&out[r0 * Nout + col] = make_float2(v0, v1);
            if (r1 < M) *(float2*)&out[r1 * Nout + col] = make_float2(v2, v3);
        }
    }
}

// ---------------- host ----------------
extern "C" void kernel_launch(void* const* d_in, const int* in_sizes, int n_in,
                              void* d_out, int out_size) {
    const float* x = nullptr;
    const int *src = nullptr, *dstp = nullptr;
    const float* Ws[3] = {0, 0, 0};
    const float* Wn[3] = {0, 0, 0};
    const float* bs[3] = {0, 0, 0};
    int c65536 = 0, c256 = 0, c32768 = 0, c800k = 0;
    for (int i = 0; i < n_in; i++) {
        int sz = in_sizes[i];
        void* p = d_in[i];
        if (sz == 12800000) {
            x = (const float*)p;
        } else if (sz == 800000) {
            if (c800k++ == 0) src = (const int*)p; else dstp = (const int*)p;
        } else if (sz == 65536) {
            int k = c65536++;
            if (k == 0) Ws[0] = (const float*)p;
            else if (k == 1) Wn[0] = (const float*)p;
            else if (k == 2) Ws[1] = (const float*)p;
            else Wn[1] = (const float*)p;
        } else if (sz == 32768) {
            if (c32768++ == 0) Ws[2] = (const float*)p; else Wn[2] = (const float*)p;
        } else if (sz == 256) {
            if (c256++ == 0) bs[0] = (const float*)p; else bs[1] = (const float*)p;
        } else if (sz == 128) {
            bs[2] = (const float*)p;
        }
    }

    float *agg, *bufA, *bufB;
    int* degp;
    cudaGetSymbolAddress((void**)&agg,  g_agg);
    cudaGetSymbolAddress((void**)&bufA, g_bufA);
    cudaGetSymbolAddress((void**)&bufB, g_bufB);
    cudaGetSymbolAddress((void**)&degp, g_deg);

    const int n = N_NODES, e = N_EDGES;

    // CSR build
    cudaMemsetAsync(degp, 0, n * sizeof(int));
    k_count<<<(e + 255) / 256, 256>>>(dstp, e);
    k_scan<<<1, 1024>>>(n);
    k_init_cur<<<(n + 255) / 256, 256>>>(n);
    k_fill<<<(e + 255) / 256, 256>>>(src, dstp, e);

    dim3 aggBlk(64, 4);
    int aggGrid = (n + 3) / 4;
    float* outp = (float*)d_out;

    dim3 g01((n + GBM - 1) / GBM, 256 / GBN);
    dim3 g2 ((n + GBM - 1) / GBM, 128 / GBN);

    // layer 0
    k_agg<<<aggGrid, aggBlk>>>(x, agg, n);
    k_gemm_tf32<<<g01, 256>>>(x, agg, Ws[0], Wn[0], bs[0], bufA, n, 256, 256, 1);
    // layer 1
    k_agg<<<aggGrid, aggBlk>>>(bufA, agg, n);
    k_gemm_tf32<<<g01, 256>>>(bufA, agg, Ws[1], Wn[1], bs[1], bufB, n, 256, 256, 1);
    // layer 2 (no relu) -> d_out
    k_agg<<<aggGrid, aggBlk>>>(bufB, agg, n);
    k_gemm_tf32<<<g2, 256>>>(bufB, agg, Ws[2], Wn[2], bs[2], outp, n, 128, 256, 0);
}

// round 4
// speedup vs baseline: 3.0482x; 1.7287x over previous
#include <cuda_runtime.h>
#include <cuda_fp16.h>
#include <cstdint>

#define N_NODES 50000
#define N_EDGES 800000

// ---------------- scratch (no allocations allowed) ----------------
__device__ __align__(16) __half g_h16 [N_NODES * 256];
__device__ __align__(16) __half g_h16b[N_NODES * 256];
__device__ __align__(16) __half g_agg16[N_NODES * 256];
__device__ __align__(16) __half g_w16[327680];
__device__ int g_deg[N_NODES];
__device__ int g_row[N_NODES + 1];
__device__ int g_cur[N_NODES];
__device__ int g_csr[N_EDGES];

// ---------------- fp32 -> fp16 convert ----------------
__global__ void k_cvt(const float* __restrict__ in, __half* __restrict__ out, int n) {
    int i = (blockIdx.x * blockDim.x + threadIdx.x) * 4;
    if (i < n) {
        float4 v = *(const float4*)(in + i);
        __half2 a = __floats2half2_rn(v.x, v.y);
        __half2 b = __floats2half2_rn(v.z, v.w);
        uint2 o;
        o.x = *(uint32_t*)&a;
        o.y = *(uint32_t*)&b;
        *(uint2*)(out + i) = o;
    }
}

// ---------------- CSR build ----------------
__global__ void k_count(const int* __restrict__ dst, int e) {
    int i = blockIdx.x * blockDim.x + threadIdx.x;
    if (i < e) atomicAdd(&g_deg[dst[i]], 1);
}

// single-block scan with warp shuffles
__global__ void k_scan(int n) {
    __shared__ int wsum[32];
    __shared__ int carry;
    int lane = threadIdx.x & 31, wid = threadIdx.x >> 5;
    if (threadIdx.x == 0) { carry = 0; g_row[0] = 0; }
    __syncthreads();
    for (int base = 0; base < n; base += 1024) {
        int i = base + threadIdx.x;
        int v = (i < n) ? g_deg[i] : 0;
        int x = v;
#pragma unroll
        for (int o = 1; o < 32; o <<= 1) {
            int t = __shfl_up_sync(0xffffffffu, x, o);
            if (lane >= o) x += t;
        }
        if (lane == 31) wsum[wid] = x;
        __syncthreads();
        if (wid == 0) {
            int w = wsum[lane];
#pragma unroll
            for (int o = 1; o < 32; o <<= 1) {
                int t = __shfl_up_sync(0xffffffffu, w, o);
                if (lane >= o) w += t;
            }
            wsum[lane] = w;
        }
        __syncthreads();
        int incl = x + (wid ? wsum[wid - 1] : 0) + carry;
        if (i < n) g_row[i + 1] = incl;
        __syncthreads();
        if (threadIdx.x == 1023) carry = incl;
        __syncthreads();
    }
}

__global__ void k_init_cur(int n) {
    int i = blockIdx.x * blockDim.x + threadIdx.x;
    if (i < n) g_cur[i] = g_row[i];
}

__global__ void k_fill(const int* __restrict__ src, const int* __restrict__ dst, int e) {
    int i = blockIdx.x * blockDim.x + threadIdx.x;
    if (i < e) {
        int p = atomicAdd(&g_cur[dst[i]], 1);
        g_csr[p] = src[i];
    }
}

// ---------------- mean aggregation on fp16 (fp32 accumulate) ----------------
__global__ void k_agg16(const __half* __restrict__ h, __half* __restrict__ agg, int n) {
    int v = blockIdx.x * 4 + threadIdx.y;
    if (v >= n) return;
    int s = g_row[v], e = g_row[v + 1];
    const uint2* h4 = (const uint2*)h;   // 4 halves per uint2
    int tx = threadIdx.x;                // 0..63 -> 256 halves
    float a0 = 0.f, a1 = 0.f, a2 = 0.f, a3 = 0.f;
    int i = s;
    for (; i + 2 <= e; i += 2) {
        int u0 = g_csr[i], u1 = g_csr[i + 1];
        uint2 t0 = __ldg(&h4[u0 * 64 + tx]);
        uint2 t1 = __ldg(&h4[u1 * 64 + tx]);
        float2 p0 = __half22float2(*(__half2*)&t0.x);
        float2 p1 = __half22float2(*(__half2*)&t0.y);
        float2 q0 = __half22float2(*(__half2*)&t1.x);
        float2 q1 = __half22float2(*(__half2*)&t1.y);
        a0 += p0.x + q0.x; a1 += p0.y + q0.y;
        a2 += p1.x + q1.x; a3 += p1.y + q1.y;
    }
    if (i < e) {
        uint2 t0 = __ldg(&h4[g_csr[i] * 64 + tx]);
        float2 p0 = __half22float2(*(__half2*)&t0.x);
        float2 p1 = __half22float2(*(__half2*)&t0.y);
        a0 += p0.x; a1 += p0.y; a2 += p1.x; a3 += p1.y;
    }
    float inv = 1.0f / (float)max(e - s, 1);
    __half2 o0 = __floats2half2_rn(a0 * inv, a1 * inv);
    __half2 o1 = __floats2half2_rn(a2 * inv, a3 * inv);
    uint2 o;
    o.x = *(uint32_t*)&o0;
    o.y = *(uint32_t*)&o1;
    ((uint2*)agg)[v * 64 + tx] = o;
}

// ---------------- fp16 tensor-core dual GEMM ----------------
// out = X1@W1^T + X2@W2^T + b. X,W in fp16; fp32 accumulate.
// Block 128(M) x 128(N) x 32(K), 8 warps (4M x 2N), warp tile 32x64.
// 2-stage cp.async double buffer. PADK=40 halves/row (80B, conflict-free).

#define PADK 40

__device__ __forceinline__ void ldm_x4(uint32_t& r0, uint32_t& r1, uint32_t& r2,
                                       uint32_t& r3, uint32_t addr) {
    asm volatile("ldmatrix.sync.aligned.m8n8.x4.shared.b16 {%0,%1,%2,%3}, [%4];"
                 : "=r"(r0), "=r"(r1), "=r"(r2), "=r"(r3) : "r"(addr));
}

__device__ __forceinline__ void mma16816(float* c, const uint32_t* a, const uint32_t* b) {
    asm volatile(
        "mma.sync.aligned.m16n8k16.row.col.f32.f16.f16.f32 "
        "{%0,%1,%2,%3}, {%4,%5,%6,%7}, {%8,%9}, {%0,%1,%2,%3};"
        : "+f"(c[0]), "+f"(c[1]), "+f"(c[2]), "+f"(c[3])
        : "r"(a[0]), "r"(a[1]), "r"(a[2]), "r"(a[3]), "r"(b[0]), "r"(b[1]));
}

__device__ __forceinline__ void cpa16(uint32_t sdst, const void* gsrc, int sz) {
    asm volatile("cp.async.ca.shared.global [%0], [%1], 16, %2;"
                 :: "r"(sdst), "l"(gsrc), "r"(sz));
}

template <int OUT_HALF>
__global__ __launch_bounds__(256, 2) void k_gemm16(
    const __half* __restrict__ X1, const __half* __restrict__ X2,
    const __half* __restrict__ W1, const __half* __restrict__ W2,
    const float* __restrict__ bias, void* __restrict__ outv,
    int M, int Nout, int relu)
{
    __shared__ __align__(16) __half As[2][128 * PADK];
    __shared__ __align__(16) __half Bs[2][128 * PADK];

    int tid = threadIdx.x, lane = tid & 31, warp = tid >> 5;
    int wm = warp >> 1, wn = warp & 1;
    int bm = blockIdx.x * 128, bn = blockIdx.y * 128;

    uint32_t sA0 = (uint32_t)__cvta_generic_to_shared(&As[0][0]);
    uint32_t sA1 = (uint32_t)__cvta_generic_to_shared(&As[1][0]);
    uint32_t sB0 = (uint32_t)__cvta_generic_to_shared(&Bs[0][0]);
    uint32_t sB1 = (uint32_t)__cvta_generic_to_shared(&Bs[1][0]);

    float acc[2][8][4];
#pragma unroll
    for (int mi = 0; mi < 2; mi++)
#pragma unroll
        for (int ni = 0; ni < 8; ni++)
#pragma unroll
            for (int r = 0; r < 4; r++) acc[mi][ni][r] = 0.f;

    // cp.async staging: thread -> (row = tid>>1, two 8-half chunks)
    int r = tid >> 1;
    int cbase = (tid & 1) * 2;
    int arow = min(bm + r, M - 1);
    int asz = (bm + r < M) ? 16 : 0;
    int brow = bn + r;

#define ISSUE(st) do {                                                        \
    int p_ = (st) >> 3, kk_ = ((st) & 7) * 32;                                \
    const __half* X_ = p_ ? X2 : X1;                                          \
    const __half* W_ = p_ ? W2 : W1;                                          \
    uint32_t dA_ = ((st) & 1) ? sA1 : sA0;                                    \
    uint32_t dB_ = ((st) & 1) ? sB1 : sB0;                                    \
    _Pragma("unroll")                                                         \
    for (int c_ = 0; c_ < 2; c_++) {                                          \
        int ch_ = cbase + c_;                                                 \
        cpa16(dA_ + (r * PADK + ch_ * 8) * 2, X_ + arow * 256 + kk_ + ch_ * 8, asz); \
        cpa16(dB_ + (r * PADK + ch_ * 8) * 2, W_ + brow * 256 + kk_ + ch_ * 8, 16);  \
    }                                                                         \
    asm volatile("cp.async.commit_group;");                                   \
} while (0)

    ISSUE(0);
    ISSUE(1);

    int g = lane >> 2, cq = lane & 3;
    int j = lane & 7, t = lane >> 3;

    for (int it = 0; it < 16; ++it) {
        if (it < 15) asm volatile("cp.async.wait_group 1;");
        else         asm volatile("cp.async.wait_group 0;");
        __syncthreads();
        uint32_t bA = (it & 1) ? sA1 : sA0;
        uint32_t bB = (it & 1) ? sB1 : sB0;
#pragma unroll
        for (int k16 = 0; k16 < 2; k16++) {
            int kh0 = k16 * 16;
            uint32_t a[2][4];
#pragma unroll
            for (int mi = 0; mi < 2; mi++) {
                int rowa = wm * 32 + mi * 16 + j + (t & 1) * 8;
                int cola = kh0 + (t >> 1) * 8;
                ldm_x4(a[mi][0], a[mi][1], a[mi][2], a[mi][3],
                       bA + (rowa * PADK + cola) * 2);
            }
            uint32_t b[8][2];
#pragma unroll
            for (int q = 0; q < 4; q++) {
                int rowb = wn * 64 + q * 16 + j + (t >> 1) * 8;
                int colb = kh0 + (t & 1) * 8;
                uint32_t r0, r1, r2, r3;
                ldm_x4(r0, r1, r2, r3, bB + (rowb * PADK + colb) * 2);
                b[2 * q][0] = r0; b[2 * q][1] = r1;
                b[2 * q + 1][0] = r2; b[2 * q + 1][1] = r3;
            }
#pragma unroll
            for (int mi = 0; mi < 2; mi++)
#pragma unroll
                for (int ni = 0; ni < 8; ni++)
                    mma16816(acc[mi][ni], a[mi], b[ni]);
        }
        if (it < 14) {
            __syncthreads();
            ISSUE(it + 2);
        }
    }

    // epilogue
#pragma unroll
    for (int mi = 0; mi < 2; mi++) {
        int r0 = bm + wm * 32 + mi * 16 + g;
        int r1 = r0 + 8;
#pragma unroll
        for (int ni = 0; ni < 8; ni++) {
            int col = bn + wn * 64 + ni * 8 + 2 * cq;
            float bx = bias[col], by = bias[col + 1];
            float v0 = acc[mi][ni][0] + bx;
            float v1 = acc[mi][ni][1] + by;
            float v2 = acc[mi][ni][2] + bx;
            float v3 = acc[mi][ni][3] + by;
            if (relu) {
                v0 = fmaxf(v0, 0.f); v1 = fmaxf(v1, 0.f);
                v2 = fmaxf(v2, 0.f); v3 = fmaxf(v3, 0.f);
            }
            if (OUT_HALF) {
                __half* o = (__half*)outv;
                if (r0 < M) *(__half2*)&o[r0 * Nout + col] = __floats2half2_rn(v0, v1);
                if (r1 < M) *(__half2*)&o[r1 * Nout + col] = __floats2half2_rn(v2, v3);
            } else {
                float* o = (float*)outv;
                if (r0 < M) *(float2*)&o[r0 * Nout + col] = make_float2(v0, v1);
                if (r1 < M) *(float2*)&o[r1 * Nout + col] = make_float2(v2, v3);
            }
        }
    }
#undef ISSUE
}

// ---------------- host ----------------
extern "C" void kernel_launch(void* const* d_in, const int* in_sizes, int n_in,
                              void* d_out, int out_size) {
    const float* x = nullptr;
    const int *src = nullptr, *dstp = nullptr;
    const float* Ws[3] = {0, 0, 0};
    const float* Wn[3] = {0, 0, 0};
    const float* bs[3] = {0, 0, 0};
    int c65536 = 0, c256 = 0, c32768 = 0, c800k = 0;
    for (int i = 0; i < n_in; i++) {
        int sz = in_sizes[i];
        void* p = d_in[i];
        if (sz == 12800000) {
            x = (const float*)p;
        } else if (sz == 800000) {
            if (c800k++ == 0) src = (const int*)p; else dstp = (const int*)p;
        } else if (sz == 65536) {
            int k = c65536++;
            if (k == 0) Ws[0] = (const float*)p;
            else if (k == 1) Wn[0] = (const float*)p;
            else if (k == 2) Ws[1] = (const float*)p;
            else Wn[1] = (const float*)p;
        } else if (sz == 32768) {
            if (c32768++ == 0) Ws[2] = (const float*)p; else Wn[2] = (const float*)p;
        } else if (sz == 256) {
            if (c256++ == 0) bs[0] = (const float*)p; else bs[1] = (const float*)p;
        } else if (sz == 128) {
            bs[2] = (const float*)p;
        }
    }

    __half *h16, *h16b, *agg16, *w16;
    int* degp;
    cudaGetSymbolAddress((void**)&h16,   g_h16);
    cudaGetSymbolAddress((void**)&h16b,  g_h16b);
    cudaGetSymbolAddress((void**)&agg16, g_agg16);
    cudaGetSymbolAddress((void**)&w16,   g_w16);
    cudaGetSymbolAddress((void**)&degp,  g_deg);

    const int n = N_NODES, e = N_EDGES;

    // convert inputs to fp16
    k_cvt<<<12500, 256>>>(x, h16, n * 256);
    k_cvt<<<64, 256>>>(Ws[0], w16 + 0,      65536);
    k_cvt<<<64, 256>>>(Wn[0], w16 + 65536,  65536);
    k_cvt<<<64, 256>>>(Ws[1], w16 + 131072, 65536);
    k_cvt<<<64, 256>>>(Wn[1], w16 + 196608, 65536);
    k_cvt<<<32, 256>>>(Ws[2], w16 + 262144, 32768);
    k_cvt<<<32, 256>>>(Wn[2], w16 + 294912, 32768);

    // CSR build
    cudaMemsetAsync(degp, 0, n * sizeof(int));
    k_count<<<(e + 255) / 256, 256>>>(dstp, e);
    k_scan<<<1, 1024>>>(n);
    k_init_cur<<<(n + 255) / 256, 256>>>(n);
    k_fill<<<(e + 255) / 256, 256>>>(src, dstp, e);

    dim3 aggBlk(64, 4);
    int aggGrid = (n + 3) / 4;
    int gx = (n + 127) / 128;
    dim3 g01(gx, 2);
    dim3 g2(gx, 1);

    // layer 0: x16 -> h16b
    k_agg16<<<aggGrid, aggBlk>>>(h16, agg16, n);
    k_gemm16<1><<<g01, 256>>>(h16, agg16, w16 + 0, w16 + 65536, bs[0], h16b, n, 256, 1);
    // layer 1: h16b -> h16
    k_agg16<<<aggGrid, aggBlk>>>(h16b, agg16, n);
    k_gemm16<1><<<g01, 256>>>(h16b, agg16, w16 + 131072, w16 + 196608, bs[1], h16, n, 256, 1);
    // layer 2: h16 -> d_out (fp32)
    k_agg16<<<aggGrid, aggBlk>>>(h16, agg16, n);
    k_gemm16<0><<<g2, 256>>>(h16, agg16, w16 + 262144, w16 + 294912, bs[2], d_out, n, 128, 0);
}